// round 4
// baseline (speedup 1.0000x reference)
#include <cuda_runtime.h>
#include <cstddef>

#define NEGV -1000000000.0f
#define HDIM 128
#define NMAX 12288

// per-node partials: g_p[n].x = h[n].W[0:128], g_p[n].y = h[n].W[128:256)
__device__ float2 g_p[NMAX];
__device__ int g_done;

__global__ void reset_kernel() {
    g_done = 0;
}

__global__ void __launch_bounds__(256)
fused_kernel(const float* __restrict__ h,
             const int* __restrict__ sources,
             const int* __restrict__ dests,
             const float* __restrict__ weights,
             const float* __restrict__ W,
             const float* __restrict__ b,
             float* __restrict__ out,
             int N, int E, int n4,
             int nPartialBlks, int nFillBlks, int nScatterBlks) {
    const int bid = blockIdx.x;
    const int tid = threadIdx.x;
    const int target = nPartialBlks + nFillBlks;

    if (bid < nPartialBlks) {
        // ---- node partials: 8 lanes per node, 4 nodes per warp, 32 per block
        const int warp = tid >> 5;
        const int lane = tid & 31;
        const int sub  = lane & 7;        // lane within 8-lane group
        const int grp  = lane >> 3;       // node within warp
        const int node = bid * 32 + warp * 4 + grp;

        if (node < N) {
            const float* hp = h + (size_t)node * HDIM + sub * 16;
            const float* wp = W + sub * 16;
            float ad = 0.0f, as = 0.0f;
            #pragma unroll
            for (int k = 0; k < 4; k++) {
                const float4 hv = *reinterpret_cast<const float4*>(hp + k * 4);
                const float4 wd = *reinterpret_cast<const float4*>(wp + k * 4);
                const float4 ws = *reinterpret_cast<const float4*>(wp + HDIM + k * 4);
                ad += hv.x * wd.x + hv.y * wd.y + hv.z * wd.z + hv.w * wd.w;
                as += hv.x * ws.x + hv.y * ws.y + hv.z * ws.z + hv.w * ws.w;
            }
            #pragma unroll
            for (int o = 4; o; o >>= 1) {
                ad += __shfl_xor_sync(0xffffffffu, ad, o);
                as += __shfl_xor_sync(0xffffffffu, as, o);
            }
            if (sub == 0) g_p[node] = make_float2(ad, as);
        }
        __syncthreads();
        if (tid == 0) {
            __threadfence();
            atomicAdd(&g_done, 1);
        }
    } else if (bid < nPartialBlks + nFillBlks) {
        // ---- fill: each block writes 1024 float4s (4 per thread), streaming
        const int fbid = bid - nPartialBlks;
        float4* o4 = (float4*)out;
        const float4 v = make_float4(NEGV, NEGV, NEGV, NEGV);
        int base = fbid * 1024 + tid;
        #pragma unroll
        for (int k = 0; k < 4; k++) {
            int idx = base + k * 256;
            if (idx < n4) __stcs(&o4[idx], v);
        }
        __syncthreads();
        if (tid == 0) {
            __threadfence();
            atomicAdd(&g_done, 1);
        }
    } else {
        // ---- scatter: wait for partials + fill, then overwrite edge entries
        if (tid == 0) {
            volatile int* dp = &g_done;
            while (*dp < target) __nanosleep(128);
        }
        __syncthreads();
        __threadfence();

        const float wW = W[2 * HDIM];
        const float bb = b[0];
        const int sbid = bid - target;
        const int stride = nScatterBlks * 256;
        for (int e = sbid * 256 + tid; e < E; e += stride) {
            int s = sources[e];
            int d = dests[e];
            float val = g_p[d].x + g_p[s].y + weights[e] * wW + bb;
            out[(size_t)d * N + s] = val;
        }
    }
}

extern "C" void kernel_launch(void* const* d_in, const int* in_sizes, int n_in,
                              void* d_out, int out_size) {
    const float* h       = (const float*)d_in[0];
    const int*   sources = (const int*)d_in[1];
    const int*   dests   = (const int*)d_in[2];
    const float* weights = (const float*)d_in[3];
    const float* W       = (const float*)d_in[4];
    const float* b       = (const float*)d_in[5];
    float* out = (float*)d_out;

    const int N = in_sizes[0] / HDIM;     // 12288
    const int E = in_sizes[1];            // 393216

    long long total = (long long)N * N;
    int n4 = (int)(total >> 2);                       // 37,748,736

    int nPartialBlks = (N + 31) / 32;                 // 384
    int nFillBlks    = (n4 + 1023) / 1024;            // 36,864
    int nScatterBlks = 256;                           // < min concurrent slots: no deadlock

    reset_kernel<<<1, 1>>>();
    fused_kernel<<<nPartialBlks + nFillBlks + nScatterBlks, 256>>>(
        h, sources, dests, weights, W, b, out,
        N, E, n4, nPartialBlks, nFillBlks, nScatterBlks);
}